// round 16
// baseline (speedup 1.0000x reference)
#include <cuda_runtime.h>
#include <cuda_bf16.h>
#include <cstdint>

#define NB    262144
#define NT    256            // 8 warps x 16 rows = 128 rows/CTA
#define GRID  2048

// Weight rows: 272B linear stride (272 ≡ 4 words mod 32 banks -> 8-row
// ldmatrix groups conflict-free). 16 chunks of 16B: 0-7 hi bf16, 8-15 lo.
#define W0_OFF   0           // 4 stages x 56 rows x 272B (W_in as [n=j][k])
#define W0_STG   15232
#define W12_OFF  60928       // 4 stages x 128 rows x 272B (0-63 W_mu, 64-127 W_sig)
#define W12_STG  34816
#define BIN_OFF  200192      // f32 [4][64]
#define BMU_OFF  201216      // f32 [4][64]
#define BSIG_OFF 202240      // f32 [4][64]
#define SMEM_TOTAL 203264

__device__ __forceinline__ uint32_t smem_u32(const void* p) {
    uint32_t a;
    asm("{ .reg .u64 t; cvta.to.shared.u64 t, %1; cvt.u32.u64 %0, t; }" : "=r"(a) : "l"(p));
    return a;
}
__device__ __forceinline__ float rcpa(float x) {
    float r; asm("rcp.approx.f32 %0,%1;" : "=f"(r) : "f"(x)); return r;
}
__device__ __forceinline__ float tanh_fast(float x) {   // 2*sigmoid(2x)-1
    float e = __expf(-2.0f * x);
    return __fmaf_rn(2.0f, rcpa(1.0f + e), -1.0f);
}

__device__ __forceinline__ void mma16816(float* d, const uint32_t* a, const uint32_t* b) {
    asm volatile("mma.sync.aligned.m16n8k16.row.col.f32.bf16.bf16.f32 "
        "{%0,%1,%2,%3}, {%4,%5,%6,%7}, {%8,%9}, {%0,%1,%2,%3};"
        : "+f"(d[0]), "+f"(d[1]), "+f"(d[2]), "+f"(d[3])
        : "r"(a[0]), "r"(a[1]), "r"(a[2]), "r"(a[3]), "r"(b[0]), "r"(b[1]));
}
template<int IMM>
__device__ __forceinline__ void ldm4o(uint32_t* r, uint32_t a) {
    asm volatile("ldmatrix.sync.aligned.m8n8.x4.shared.b16 {%0,%1,%2,%3}, [%4+%5];"
        : "=r"(r[0]), "=r"(r[1]), "=r"(r[2]), "=r"(r[3]) : "r"(a), "n"(IMM));
}
template<int IMM>
__device__ __forceinline__ void ldm2o(uint32_t* r, uint32_t a) {
    asm volatile("ldmatrix.sync.aligned.m8n8.x2.shared.b16 {%0,%1}, [%2+%3];"
        : "=r"(r[0]), "=r"(r[1]) : "r"(a), "n"(IMM));
}

// pack (x,y) into hi-bf16x2 h and residual-lo-bf16x2 l (low half = x)
__device__ __forceinline__ void packhl(float x, float y, uint32_t &h, uint32_t &l) {
    asm("cvt.rn.bf16x2.f32 %0, %1, %2;" : "=r"(h) : "f"(y), "f"(x));
    float h0 = __uint_as_float(h << 16);
    float h1 = __uint_as_float(h & 0xffff0000u);
    asm("cvt.rn.bf16x2.f32 %0, %1, %2;" : "=r"(l) : "f"(y - h1), "f"(x - h0));
}
// reconstruct (x,y) = hi + lo
__device__ __forceinline__ void unpackadd(uint32_t h, uint32_t l, float &x, float &y) {
    x = __uint_as_float(h << 16)         + __uint_as_float(l << 16);
    y = __uint_as_float(h & 0xffff0000u) + __uint_as_float(l & 0xffff0000u);
}

// weight element -> hi/lo bf16 at linear [row][chunk] position
__device__ __forceinline__ void store_w(char* smem, int base, int row, int k, float v) {
    __nv_bfloat16 hb = __float2bfloat16(v);
    __nv_bfloat16 lb = __float2bfloat16(v - __bfloat162float(hb));
    char* r = smem + base + row*272 + ((k >> 3) << 4) + (k & 7)*2;
    *(__nv_bfloat16*)(r)       = hb;
    *(__nv_bfloat16*)(r + 128) = lb;     // lo chunk = hi chunk + 8 -> +128B
}

// update one packed zout pair: z = z*sigmoid(ds+bs) + (dm+bm); logdet accum
__device__ __forceinline__ void upd_pair(uint32_t &zh, uint32_t &zl,
    float dm0, float dm1, float ds0, float ds1,
    float bm0, float bm1, float bs0, float bs1, float &ld)
{
    float h0, h1; unpackadd(zh, zl, h0, h1);
    float t0 = ds0 + bs0, t1 = ds1 + bs1;
    float e0 = __expf(-t0), e1 = __expf(-t1);
    float u0 = 1.f + e0, u1 = 1.f + e1;
    float f0 = h0 * rcpa(u0) + (dm0 + bm0);
    float f1 = h1 * rcpa(u1) + (dm1 + bm1);
    ld -= __logf(u0) + __logf(u1);
    packhl(f0, f1, zh, zl);
}

// ---- coupling macros: all ldmatrix offsets are compile-time immediates ----
#define G1K(P, KC) do {                                                        \
    uint32_t bh[4], bl[4];                                                     \
    ldm4o<(P)*4352 + (KC)*32>(bh, W0b);                                        \
    mma16816(d0a, aH[KC], bh);     mma16816(d1a, aH[KC], bh + 2);              \
    mma16816(d0b, aL[KC], bh);     mma16816(d1b, aL[KC], bh + 2);              \
    ldm4o<(P)*4352 + (KC)*32 + 128>(bl, W0b);                                  \
    mma16816(d0b, aH[KC], bl);     mma16816(d1b, aH[KC], bl + 2);              \
} while (0)

#define G1P(P) do {                                                            \
    float d0a[4]={0,0,0,0}, d0b[4]={0,0,0,0};                                  \
    float d1a[4]={0,0,0,0}, d1b[4]={0,0,0,0};                                  \
    G1K(P,0); G1K(P,1); G1K(P,2); G1K(P,3);                                    \
    float b00 = bin_s[16*(P) + 2*t],     b01 = bin_s[16*(P) + 2*t + 1];        \
    float b10 = bin_s[16*(P) + 8 + 2*t], b11 = bin_s[16*(P) + 8 + 2*t + 1];    \
    float v0 = tanh_fast(d0a[0] + d0b[0] + b00);                               \
    float v1 = tanh_fast(d0a[1] + d0b[1] + b01);                               \
    float v2 = tanh_fast(d0a[2] + d0b[2] + b00);                               \
    float v3 = tanh_fast(d0a[3] + d0b[3] + b01);                               \
    float w0 = tanh_fast(d1a[0] + d1b[0] + b10);                               \
    float w1 = tanh_fast(d1a[1] + d1b[1] + b11);                               \
    float w2 = tanh_fast(d1a[2] + d1b[2] + b10);                               \
    float w3 = tanh_fast(d1a[3] + d1b[3] + b11);                               \
    packhl(v0, v1, hH[P][0], hL[P][0]);                                        \
    packhl(v2, v3, hH[P][1], hL[P][1]);                                        \
    packhl(w0, w1, hH[P][2], hL[P][2]);                                        \
    packhl(w2, w3, hH[P][3], hL[P][3]);                                        \
} while (0)

#define G16K(KC) do {                                                          \
    uint32_t bh[2], bl[2];                                                     \
    ldm2o<13056 + (KC)*32>(bh, W0b2);                                          \
    mma16816(da, aH[KC], bh);                                                  \
    mma16816(db, aL[KC], bh);                                                  \
    ldm2o<13056 + (KC)*32 + 128>(bl, W0b2);                                    \
    mma16816(db, aH[KC], bl);                                                  \
} while (0)

#define G2K(P, KC) do {                                                        \
    uint32_t bmh[4], bsh[4], bml[4], bsl[4];                                   \
    ldm4o<(P)*4352 + (KC)*32>(bmh, W12b);                                      \
    ldm4o<(P)*4352 + (KC)*32 + 17408>(bsh, W12b);                              \
    mma16816(m0a, hH[KC], bmh);   mma16816(m1a, hH[KC], bmh + 2);              \
    mma16816(s0a, hH[KC], bsh);   mma16816(s1a, hH[KC], bsh + 2);              \
    mma16816(m0b, hL[KC], bmh);   mma16816(m1b, hL[KC], bmh + 2);              \
    mma16816(s0b, hL[KC], bsh);   mma16816(s1b, hL[KC], bsh + 2);              \
    ldm4o<(P)*4352 + (KC)*32 + 128>(bml, W12b);                                \
    ldm4o<(P)*4352 + (KC)*32 + 17408 + 128>(bsl, W12b);                        \
    mma16816(m0b, hH[KC], bml);   mma16816(m1b, hH[KC], bml + 2);              \
    mma16816(s0b, hH[KC], bsl);   mma16816(s1b, hH[KC], bsl + 2);              \
} while (0)

#define G2P(P) do {                                                            \
    float m0a[4]={0,0,0,0}, m0b[4]={0,0,0,0}, m1a[4]={0,0,0,0}, m1b[4]={0,0,0,0};\
    float s0a[4]={0,0,0,0}, s0b[4]={0,0,0,0}, s1a[4]={0,0,0,0}, s1b[4]={0,0,0,0};\
    G2K(P,0); G2K(P,1); G2K(P,2); G2K(P,3);                                    \
    float bm0 = bmu_s[16*(P)+2*t],    bm1 = bmu_s[16*(P)+2*t+1];               \
    float bm2 = bmu_s[16*(P)+8+2*t],  bm3 = bmu_s[16*(P)+8+2*t+1];             \
    float bs0 = bsig_s[16*(P)+2*t],   bs1 = bsig_s[16*(P)+2*t+1];              \
    float bs2 = bsig_s[16*(P)+8+2*t], bs3 = bsig_s[16*(P)+8+2*t+1];            \
    upd_pair(zoH[P][0], zoL[P][0], m0a[0]+m0b[0], m0a[1]+m0b[1],               \
             s0a[0]+s0b[0], s0a[1]+s0b[1], bm0,bm1,bs0,bs1, ldA);              \
    upd_pair(zoH[P][1], zoL[P][1], m0a[2]+m0b[2], m0a[3]+m0b[3],               \
             s0a[2]+s0b[2], s0a[3]+s0b[3], bm0,bm1,bs0,bs1, ldB);              \
    upd_pair(zoH[P][2], zoL[P][2], m1a[0]+m1b[0], m1a[1]+m1b[1],               \
             s1a[0]+s1b[0], s1a[1]+s1b[1], bm2,bm3,bs2,bs3, ldA);              \
    upd_pair(zoH[P][3], zoL[P][3], m1a[2]+m1b[2], m1a[3]+m1b[3],               \
             s1a[2]+s1b[2], s1a[3]+s1b[3], bm2,bm3,bs2,bs3, ldB);              \
} while (0)

// One coupling half-step. zin (aH/aL) and zout (zoH/zoL) are packed hi/lo
// bf16 A-layout fragments [kc][r]; octet 2kc -> r 0,1; octet 2kc+1 -> r 2,3.
__device__ __forceinline__ void coupling(
    uint32_t (&aH)[4][4], uint32_t (&aL)[4][4],
    uint32_t (&zoH)[4][4], uint32_t (&zoL)[4][4],
    int s, uint32_t sb, char* smem, int lane,
    uint32_t brow4, uint32_t brow2, float& ldA, float& ldB)
{
    const int t = lane & 3;
    const uint32_t W0b  = sb + W0_OFF  + s*W0_STG  + brow4;
    const uint32_t W0b2 = sb + W0_OFF  + s*W0_STG  + brow2;
    const uint32_t W12b = sb + W12_OFF + s*W12_STG + brow4;
    const float* bin_s  = (const float*)(smem + BIN_OFF)  + s*64;
    const float* bmu_s  = (const float*)(smem + BMU_OFF)  + s*64;
    const float* bsig_s = (const float*)(smem + BSIG_OFF) + s*64;

    uint32_t hH[4][4], hL[4][4];
    // GEMM1: D1 = Z @ W0^T (n-tiles 0..6), tanh, H frags in registers
    G1P(0); G1P(1); G1P(2);
    {   // n-tile 6 (h cols 48-55; 50-55 zero via zero W0 rows + zero bias)
        float da[4]={0,0,0,0}, db[4]={0,0,0,0};
        G16K(0); G16K(1); G16K(2); G16K(3);
        float b0 = bin_s[48 + 2*t], b1 = bin_s[48 + 2*t + 1];
        float v0 = tanh_fast(da[0] + db[0] + b0);
        float v1 = tanh_fast(da[1] + db[1] + b1);
        float v2 = tanh_fast(da[2] + db[2] + b0);
        float v3 = tanh_fast(da[3] + db[3] + b1);
        packhl(v0, v1, hH[3][0], hL[3][0]);
        packhl(v2, v3, hH[3][1], hL[3][1]);
        hH[3][2] = 0u; hH[3][3] = 0u;       // octet 7 = zero pad
        hL[3][2] = 0u; hL[3][3] = 0u;
    }
    // GEMM2: [MU|SIG] = H @ [W_mu;W_sig]^T; update packed zout in place
    G2P(0); G2P(1); G2P(2); G2P(3);
}

__global__ void __launch_bounds__(NT, 1) flow_kernel(
    const float* __restrict__ g_mean, const float* __restrict__ g_logvar,
    const float* __restrict__ g_eps,
    const float* __restrict__ g_Win,  const float* __restrict__ g_bin,
    const float* __restrict__ g_Wmu,  const float* __restrict__ g_bmu,
    const float* __restrict__ g_Wsig, const float* __restrict__ g_bsig,
    float* __restrict__ g_out)
{
    extern __shared__ char smem[];
    const uint32_t sb = smem_u32(smem);
    const int tid  = threadIdx.x;
    const int warp = tid >> 5, lane = tid & 31;
    const int g = lane >> 2, t = lane & 3;

    // per-thread ldmatrix lane bases (computed once)
    const uint32_t brow4 = ((lane & 7) + ((lane >> 4) << 3))*272 + ((lane >> 3) & 1)*16;
    const uint32_t brow2 = (lane & 7)*272 + ((lane >> 3) & 1)*16;

    // zero whole SMEM (covers all pads), then stage weights hi/lo + biases
    for (int i = tid; i < SMEM_TOTAL/4; i += NT) ((uint32_t*)smem)[i] = 0u;
    __syncthreads();
    for (int i = tid; i < 4*50*64; i += NT) {                 // W_in [s][j][k]
        int s = i / 3200, r = i - s*3200, j = r >> 6, k = r & 63;
        store_w(smem, W0_OFF + s*W0_STG, j, k, g_Win[i]);
    }
    for (int i = tid; i < 4*128*50; i += NT) {                // W_mu / W_sig rows
        int s = i / 6400, r = i - s*6400, o = r / 50, k = r - o*50;
        float v = (o < 64) ? g_Wmu[s*3200 + o*50 + k] : g_Wsig[s*3200 + (o-64)*50 + k];
        store_w(smem, W12_OFF + s*W12_STG, o, k, v);
    }
    for (int i = tid; i < 200; i += NT) {
        int s = i / 50, j = i - s*50;
        ((float*)(smem + BIN_OFF))[s*64 + j] = g_bin[i];
    }
    for (int i = tid; i < 256; i += NT) {
        ((float*)(smem + BMU_OFF))[i]  = g_bmu[i];
        ((float*)(smem + BSIG_OFF))[i] = g_bsig[i];
    }
    __syncthreads();

    const size_t rowA = (size_t)blockIdx.x*128 + warp*16 + g;
    const size_t rowB = rowA + 8;

    // prologue: z built and immediately packed into hi/lo A-layout frags
    uint32_t z1H[4][4], z1L[4][4], z2H[4][4], z2L[4][4];
    float partA = 0.f, partB = 0.f;
#pragma unroll
    for (int j = 0; j < 8; j++) {
        const int kc = j >> 1, r0 = (j & 1)*2, r1 = r0 + 1;
        int c1 = 8*j + 2*t, c2 = 64 + c1;
        float2 m, l, e;
        float v0, v1, v2, v3;
        m = *(const float2*)(g_mean + rowA*128 + c1);
        l = *(const float2*)(g_logvar + rowA*128 + c1);
        e = *(const float2*)(g_eps + rowA*128 + c1);
        v0 = e.x*__expf(0.5f*l.x) + m.x;  v1 = e.y*__expf(0.5f*l.y) + m.y;
        partA += l.x + l.y + e.x*e.x + e.y*e.y;
        m = *(const float2*)(g_mean + rowB*128 + c1);
        l = *(const float2*)(g_logvar + rowB*128 + c1);
        e = *(const float2*)(g_eps + rowB*128 + c1);
        v2 = e.x*__expf(0.5f*l.x) + m.x;  v3 = e.y*__expf(0.5f*l.y) + m.y;
        partB += l.x + l.y + e.x*e.x + e.y*e.y;
        packhl(v0, v1, z1H[kc][r0], z1L[kc][r0]);
        packhl(v2, v3, z1H[kc][r1], z1L[kc][r1]);
        m = *(const float2*)(g_mean + rowA*128 + c2);
        l = *(const float2*)(g_logvar + rowA*128 + c2);
        e = *(const float2*)(g_eps + rowA*128 + c2);
        v0 = e.x*__expf(0.5f*l.x) + m.x;  v1 = e.y*__expf(0.5f*l.y) + m.y;
        partA += l.x + l.y + e.x*e.x + e.y*e.y;
        m = *(const float2*)(g_mean + rowB*128 + c2);
        l = *(const float2*)(g_logvar + rowB*128 + c2);
        e = *(const float2*)(g_eps + rowB*128 + c2);
        v2 = e.x*__expf(0.5f*l.x) + m.x;  v3 = e.y*__expf(0.5f*l.y) + m.y;
        partB += l.x + l.y + e.x*e.x + e.y*e.y;
        packhl(v0, v1, z2H[kc][r0], z2L[kc][r0]);
        packhl(v2, v3, z2H[kc][r1], z2L[kc][r1]);
    }

    float ldA = 0.f, ldB = 0.f;
#pragma unroll 1   // rolled: bounds I-cache to 2 coupling bodies
    for (int f = 0; f < 2; f++) {
        coupling(z1H, z1L, z2H, z2L, 2*f,     sb, smem, lane, brow4, brow2, ldA, ldB);
        coupling(z2H, z2L, z1H, z1L, 2*f + 1, sb, smem, lane, brow4, brow2, ldA, ldB);
    }

    // epilogue: reconstruct z, write, reduce logpz/logqz across the quad
    float sqA = 0.f, sqB = 0.f;
#pragma unroll
    for (int j = 0; j < 8; j++) {
        const int kc = j >> 1, r0 = (j & 1)*2, r1 = r0 + 1;
        int c1 = 8*j + 2*t, c2 = 64 + c1;
        float v0, v1, v2, v3;
        unpackadd(z1H[kc][r0], z1L[kc][r0], v0, v1);
        unpackadd(z1H[kc][r1], z1L[kc][r1], v2, v3);
        *(float2*)(g_out + rowA*128 + c1) = make_float2(v0, v1);
        *(float2*)(g_out + rowB*128 + c1) = make_float2(v2, v3);
        sqA += v0*v0 + v1*v1;  sqB += v2*v2 + v3*v3;
        unpackadd(z2H[kc][r0], z2L[kc][r0], v0, v1);
        unpackadd(z2H[kc][r1], z2L[kc][r1], v2, v3);
        *(float2*)(g_out + rowA*128 + c2) = make_float2(v0, v1);
        *(float2*)(g_out + rowB*128 + c2) = make_float2(v2, v3);
        sqA += v0*v0 + v1*v1;  sqB += v2*v2 + v3*v3;
    }
#pragma unroll
    for (int d = 1; d <= 2; d <<= 1) {
        sqA   += __shfl_xor_sync(0xffffffffu, sqA, d);
        sqB   += __shfl_xor_sync(0xffffffffu, sqB, d);
        partA += __shfl_xor_sync(0xffffffffu, partA, d);
        partB += __shfl_xor_sync(0xffffffffu, partB, d);
        ldA   += __shfl_xor_sync(0xffffffffu, ldA, d);
        ldB   += __shfl_xor_sync(0xffffffffu, ldB, d);
    }
    if (t == 0) {
        g_out[(size_t)NB*128 + rowA]      = -0.5f * sqA;
        g_out[(size_t)NB*128 + NB + rowA] = -0.5f * partA - ldA;
        g_out[(size_t)NB*128 + rowB]      = -0.5f * sqB;
        g_out[(size_t)NB*128 + NB + rowB] = -0.5f * partB - ldB;
    }
}

extern "C" void kernel_launch(void* const* d_in, const int* in_sizes, int n_in,
                              void* d_out, int out_size)
{
    (void)in_sizes; (void)n_in; (void)out_size;
    cudaFuncSetAttribute(flow_kernel,
                         cudaFuncAttributeMaxDynamicSharedMemorySize, SMEM_TOTAL);
    flow_kernel<<<GRID, NT, SMEM_TOTAL>>>(
        (const float*)d_in[0], (const float*)d_in[1], (const float*)d_in[2],
        (const float*)d_in[3], (const float*)d_in[4], (const float*)d_in[5],
        (const float*)d_in[6], (const float*)d_in[7], (const float*)d_in[8],
        (float*)d_out);
}